// round 7
// baseline (speedup 1.0000x reference)
#include <cuda_runtime.h>
#include <cuda_bf16.h>
#include <math.h>
#include <stdint.h>

#define N_NODES 4096
#define NFEAT   1024
#define NHID    128
#define NHEADS  8
#define NCLASS  64
#define ALPHA   0.2f
#define NEG_INF -9e15f
#define NCH32   (N_NODES / 32)   // 128 K-chunks of 32 for agg
#define NC16    (NFEAT / 16)     // 64  K-chunks of 16 for the two GEMMs

typedef uint32_t u32;

// ---------------- scratch (static device memory; no allocation) ----------------
__device__ float g_Wh  [NHEADS * N_NODES * NHID];   // 16 MB
__device__ float g_f1  [NHEADS * N_NODES];
__device__ float g_f2  [NHEADS * N_NODES];
__device__ float g_m   [NHEADS * N_NODES];
__device__ float g_hcat[N_NODES * NHEADS * NHID];   // 16 MB
__device__ float g_Who [N_NODES * NCLASS];
__device__ float g_g1  [N_NODES];
__device__ float g_g2  [N_NODES];
__device__ float g_mo  [N_NODES];
__device__ float g_obuf[N_NODES * NCLASS];
// bf16 hi/lo B-fragments for the two GEMMs
__device__ uint4 g_wfrag [NHEADS * NC16 * 16 * 32];   // W:  4 MB
__device__ uint4 g_wofrag[NC16 * 8 * 32];             // Wo: 256 KB
// int8 hi/lo B-fragments for the two attention-apply steps
__device__ uint4 g_iwhf [NHEADS * NCH32 * 16 * 32];   // Wh:  8 MB
__device__ uint4 g_iwhof[NCH32 * 8 * 32];             // Who: 512 KB
__device__ float g_S1[NHEADS * NHID];
__device__ float g_S2[NCLASS];

__device__ __forceinline__ float lrelu(float x) { return fmaxf(x, ALPHA * x); }
__device__ __forceinline__ float elu_f(float x) { return x > 0.f ? x : expm1f(x); }

__device__ __forceinline__ u32 pack_bf2(float lo, float hi) {
    __nv_bfloat162 v;
    v.x = __float2bfloat16(lo);
    v.y = __float2bfloat16(hi);
    return *(u32*)&v;
}
__device__ __forceinline__ void split2(float x, float y, u32& hi, u32& lo) {
    __nv_bfloat16 hx = __float2bfloat16(x), hy = __float2bfloat16(y);
    hi = pack_bf2(x, y);
    lo = pack_bf2(x - __bfloat162float(hx), y - __bfloat162float(hy));
}

#define MMA_BF16(ac, A0, A1, A2, A3, B0, B1) \
    asm volatile("mma.sync.aligned.m16n8k16.row.col.f32.bf16.bf16.f32 " \
                 "{%0,%1,%2,%3},{%4,%5,%6,%7},{%8,%9},{%0,%1,%2,%3};" \
                 : "+f"((ac)[0]), "+f"((ac)[1]), "+f"((ac)[2]), "+f"((ac)[3]) \
                 : "r"(A0), "r"(A1), "r"(A2), "r"(A3), "r"(B0), "r"(B1))

#define MMA_I8(ac, A0, A1, A2, A3, B0, B1) \
    asm volatile("mma.sync.aligned.m16n8k32.row.col.s32.u8.s8.s32 " \
                 "{%0,%1,%2,%3},{%4,%5,%6,%7},{%8,%9},{%0,%1,%2,%3};" \
                 : "+r"((ac)[0]), "+r"((ac)[1]), "+r"((ac)[2]), "+r"((ac)[3]) \
                 : "r"(A0), "r"(A1), "r"(A2), "r"(A3), "r"(B0), "r"(B1))

// ---------------- per-(head,col) abs-max -> int8 scale ----------------
__global__ void colmax_kernel(const float* __restrict__ M, float* __restrict__ S,
                              int rows, int cols)
{
    extern __shared__ float sm[];
    const int h = blockIdx.x, tid = threadIdx.x;
    const int d = tid % cols, rq = tid / cols;
    const int groups = blockDim.x / cols;
    const float* p = M + (size_t)h * rows * cols + d;
    float mx = 0.f;
    for (int r = rq; r < rows; r += groups)
        mx = fmaxf(mx, fabsf(p[(size_t)r * cols]));
    sm[tid] = mx;
    __syncthreads();
    if (tid < cols) {
        float m2 = sm[tid];
        for (int g = 1; g < groups; g++) m2 = fmaxf(m2, sm[g * cols + tid]);
        S[h * cols + tid] = 32000.f / fmaxf(m2, 1e-20f);
    }
}

// ---------------- prep: fp32 matrix -> bf16 hi/lo mma B fragments ----------------
// src [h][rows][cols]; dst [(h*nchunk + c)*NT + t][lane], NT = cols/8
__global__ void prep_bf16_kernel(const float* __restrict__ src, uint4* __restrict__ dst,
                                 int cols)
{
    const int c = blockIdx.x, h = blockIdx.y, tid = threadIdx.x;
    const int t = tid >> 5, l = tid & 31;
    const int tg = l & 3, g = l >> 2;
    const int NT = cols / 8;
    const int nchunk = gridDim.x;
    const float* p = src + (size_t)h * nchunk * 16 * cols
                   + (size_t)(c * 16 + tg * 2) * cols + t * 8 + g;
    float b0 = p[0], b1 = p[cols], b2 = p[8 * cols], b3 = p[9 * cols];
    uint4 v;
    split2(b0, b1, v.x, v.z);
    split2(b2, b3, v.y, v.w);
    dst[((size_t)(h * nchunk + c) * NT + t) * 32 + l] = v;
}

// ---------------- prep: fp32 matrix -> int8 hi/lo mma B fragments (k32) --------
// b0 bytes: k = c*32+tg*4+{0..3}; b1 bytes: k = c*32+16+tg*4+{0..3}; col = t*8+g
__global__ void prep_i8_kernel(const float* __restrict__ src, const float* __restrict__ S,
                               uint4* __restrict__ dst, int cols)
{
    const int c = blockIdx.x, h = blockIdx.y, tid = threadIdx.x;
    const int t = tid >> 5, l = tid & 31;
    const int tg = l & 3, g = l >> 2;
    const int NT = cols / 8;
    const int nchunk = gridDim.x;
    const int d = t * 8 + g;
    const float sc = S[h * cols + d];
    const float* p = src + (size_t)h * nchunk * 32 * cols + (size_t)c * 32 * cols + d;
    u32 hiw[2], low[2];
#pragma unroll
    for (int half = 0; half < 2; half++) {
        u32 hw = 0, lw = 0;
#pragma unroll
        for (int i = 0; i < 4; i++) {
            int k = half * 16 + tg * 4 + i;
            int w16 = __float2int_rn(p[(size_t)k * cols] * sc);
            int hi = (w16 + 128) >> 8;            // arithmetic shift
            int lo = w16 - (hi << 8);             // in [-128,127]
            hw |= ((u32)(hi & 255)) << (i * 8);
            lw |= ((u32)(lo & 255)) << (i * 8);
        }
        hiw[half] = hw; low[half] = lw;
    }
    uint4 v; v.x = hiw[0]; v.y = hiw[1]; v.z = low[0]; v.w = low[1];
    dst[((size_t)(h * nchunk + c) * NT + t) * 32 + l] = v;
}

// ---------------- split-bf16 GEMM: C[h] = A[M,1024] @ Bfrag[h] ----------------
// grid (M/128, H), 256 threads; warp w -> rows i0+w*16+{g,g+8}; NT n-tiles of 8.
template<int NT>
__global__ void __launch_bounds__(256)
gemm_bf3_kernel(const float* __restrict__ A, const uint4* __restrict__ bfrag,
                float* __restrict__ C, long cHeadStride)
{
    const int tid = threadIdx.x;
    const int w = tid >> 5, lane = tid & 31;
    const int tg = lane & 3, g = lane >> 2;
    const int h = blockIdx.y;
    const int r0 = blockIdx.x * 128 + w * 16 + g;
    const int r1 = r0 + 8;
    const int ldC = NT * 8;

    const float* A0 = A + (size_t)r0 * NFEAT;
    const float* A1 = A + (size_t)r1 * NFEAT;
    const uint4* bf = bfrag + (size_t)h * NC16 * NT * 32 + lane;

    float acc[NT][4];
#pragma unroll
    for (int t = 0; t < NT; t++)
#pragma unroll
        for (int q = 0; q < 4; q++) acc[t][q] = 0.f;

    for (int c = 0; c < NC16; c++) {
        const int kA = c * 16 + tg * 2;
        const int kB = kA + 8;
        float2 x0 = *(const float2*)(A0 + kA);
        float2 x1 = *(const float2*)(A1 + kA);
        float2 x2 = *(const float2*)(A0 + kB);
        float2 x3 = *(const float2*)(A1 + kB);
        u32 a0h, a0l, a1h, a1l, a2h, a2l, a3h, a3l;
        split2(x0.x, x0.y, a0h, a0l);
        split2(x1.x, x1.y, a1h, a1l);
        split2(x2.x, x2.y, a2h, a2l);
        split2(x3.x, x3.y, a3h, a3l);
        const uint4* bp = bf + (size_t)c * NT * 32;
#pragma unroll
        for (int t = 0; t < NT; t++) {
            uint4 b = bp[t * 32];
            MMA_BF16(acc[t], a0h, a1h, a2h, a3h, b.x, b.y);
            MMA_BF16(acc[t], a0h, a1h, a2h, a3h, b.z, b.w);
            MMA_BF16(acc[t], a0l, a1l, a2l, a3l, b.x, b.y);
        }
    }

    float* c0 = C + (size_t)h * cHeadStride + (size_t)r0 * ldC + tg * 2;
    float* c1 = C + (size_t)h * cHeadStride + (size_t)r1 * ldC + tg * 2;
#pragma unroll
    for (int t = 0; t < NT; t++) {
        *(float2*)(c0 + t * 8) = make_float2(acc[t][0], acc[t][1]);
        *(float2*)(c1 + t * 8) = make_float2(acc[t][2], acc[t][3]);
    }
}

// ---------------- per-row dot with two vectors ----------------
__global__ void dots_kernel(const float* __restrict__ Mtx, const float* __restrict__ v1,
                            const float* __restrict__ v2, float* __restrict__ o1,
                            float* __restrict__ o2, int D, int rowsPerHead, int totalRows)
{
    int warp = (blockIdx.x * blockDim.x + threadIdx.x) >> 5;
    int lane = threadIdx.x & 31;
    if (warp >= totalRows) return;
    int h = warp / rowsPerHead;
    const float* row = Mtx + (long)warp * D;
    float s1 = 0.f, s2 = 0.f;
    for (int d = lane; d < D; d += 32) {
        float x = row[d];
        s1 += x * v1[h * D + d];
        s2 += x * v2[h * D + d];
    }
#pragma unroll
    for (int o = 16; o > 0; o >>= 1) {
        s1 += __shfl_down_sync(0xffffffffu, s1, o);
        s2 += __shfl_down_sync(0xffffffffu, s2, o);
    }
    if (lane == 0) { o1[warp] = s1; o2[warp] = s2; }
}

// ---------------- layer-1 softmax max via monotone lrelu (8 heads) ----------------
__global__ void maxstat_kernel(const int* __restrict__ adj, const float* __restrict__ f1,
                               const float* __restrict__ f2, float* __restrict__ mout)
{
    __shared__ float sred[8 * 8];
    const int i = blockIdx.x, tid = threadIdx.x, wid = tid >> 5, lane = tid & 31;
    float mx[8];
#pragma unroll
    for (int h = 0; h < 8; h++) mx[h] = -INFINITY;
    const int4* arow = (const int4*)(adj + (size_t)i * N_NODES);
    for (int q = tid; q < N_NODES / 4; q += 256) {
        int4 a = arow[q];
        int j = q * 4;
#pragma unroll
        for (int h = 0; h < 8; h++) {
            float4 fv = *(const float4*)(f2 + h * N_NODES + j);
            if (a.x) mx[h] = fmaxf(mx[h], fv.x);
            if (a.y) mx[h] = fmaxf(mx[h], fv.y);
            if (a.z) mx[h] = fmaxf(mx[h], fv.z);
            if (a.w) mx[h] = fmaxf(mx[h], fv.w);
        }
    }
#pragma unroll
    for (int h = 0; h < 8; h++)
#pragma unroll
        for (int o = 16; o > 0; o >>= 1) mx[h] = fmaxf(mx[h], __shfl_xor_sync(0xffffffffu, mx[h], o));
    if (lane == 0)
#pragma unroll
        for (int h = 0; h < 8; h++) sred[h * 8 + wid] = mx[h];
    __syncthreads();
    if (tid < 8) {
        float m2 = sred[tid * 8];
#pragma unroll
        for (int w = 1; w < 8; w++) m2 = fmaxf(m2, sred[tid * 8 + w]);
        mout[tid * N_NODES + i] = (m2 == -INFINITY) ? NEG_INF
                                                    : lrelu(f1[tid * N_NODES + i] + m2);
    }
}

// ---------------- layer-2 softmax max (1 head) ----------------
__global__ void maxstat1_kernel(const int* __restrict__ adj, const float* __restrict__ g1,
                                const float* __restrict__ g2, float* __restrict__ mout)
{
    __shared__ float sred[8];
    const int i = blockIdx.x, tid = threadIdx.x, wid = tid >> 5, lane = tid & 31;
    float mx = -INFINITY;
    const int4* arow = (const int4*)(adj + (size_t)i * N_NODES);
    for (int q = tid; q < N_NODES / 4; q += 256) {
        int4 a = arow[q];
        float4 fv = *(const float4*)(g2 + q * 4);
        if (a.x) mx = fmaxf(mx, fv.x);
        if (a.y) mx = fmaxf(mx, fv.y);
        if (a.z) mx = fmaxf(mx, fv.z);
        if (a.w) mx = fmaxf(mx, fv.w);
    }
#pragma unroll
    for (int o = 16; o > 0; o >>= 1) mx = fmaxf(mx, __shfl_xor_sync(0xffffffffu, mx, o));
    if (lane == 0) sred[wid] = mx;
    __syncthreads();
    if (tid == 0) {
        float m2 = sred[0];
        for (int w = 1; w < 8; w++) m2 = fmaxf(m2, sred[w]);
        mout[i] = (m2 == -INFINITY) ? NEG_INF : lrelu(g1[i] + m2);
    }
}

// ---------------- int8 IMMA attention apply ----------------
// grid (M/64, H), 128 threads (4 warps); warp w -> rows i0+w*16+{g,g+8}.
// P quantized to u16 (u8 hi/lo); B prequantized s16 (s8 hi/lo) with per-col scale.
// 3 IMMA terms per (k32-chunk, tile): hi*hi -> acch, hi*lo + lo*hi -> accm.
template<int NT>
__global__ void __launch_bounds__(128)
agg_i8_kernel(const int* __restrict__ adj, const float* __restrict__ f1,
              const float* __restrict__ f2, const float* __restrict__ mrow,
              const uint4* __restrict__ ifrag, const float* __restrict__ S,
              float* __restrict__ out, int ldOut, int colOffMult)
{
    const int tid = threadIdx.x;
    const int w = tid >> 5, lane = tid & 31;
    const int tg = lane & 3, g = lane >> 2;
    const int h = blockIdx.y;
    const int i0 = blockIdx.x * 64;
    const int hN = h * N_NODES;
    const int r0 = i0 + w * 16 + g;
    const int r1 = r0 + 8;

    const float f1a = f1[hN + r0], ma = mrow[hN + r0];
    const float f1b = f1[hN + r1], mb = mrow[hN + r1];
    const int* adjA = adj + (size_t)r0 * N_NODES;
    const int* adjB = adj + (size_t)r1 * N_NODES;
    const float* f2h = f2 + hN;
    const uint4* bf = ifrag + (size_t)h * NCH32 * NT * 32 + lane;
    const float* Sh = S + h * NT * 8;

    int acch[NT][4], accm[NT][4];
#pragma unroll
    for (int t = 0; t < NT; t++)
#pragma unroll
        for (int q = 0; q < 4; q++) { acch[t][q] = 0; accm[t][q] = 0; }

    float z0 = 0.f, z1 = 0.f;

    for (int c = 0; c < NCH32; c++) {
        const int jA = c * 32 + tg * 4;
        const int jB = jA + 16;

        u32 AhL, AlL, AhH, AlH, BhL, BlL, BhH, BlH;
        // row r0, k-low
        {
            int4 a = *(const int4*)(adjA + jA);
            float4 f = *(const float4*)(f2h + jA);
            float p0 = __expf((a.x ? lrelu(f1a + f.x) : NEG_INF) - ma);
            float p1 = __expf((a.y ? lrelu(f1a + f.y) : NEG_INF) - ma);
            float p2 = __expf((a.z ? lrelu(f1a + f.z) : NEG_INF) - ma);
            float p3 = __expf((a.w ? lrelu(f1a + f.w) : NEG_INF) - ma);
            z0 += (p0 + p1) + (p2 + p3);
            u32 q0 = (u32)(p0 * 65535.f + 0.5f), q1 = (u32)(p1 * 65535.f + 0.5f);
            u32 q2 = (u32)(p2 * 65535.f + 0.5f), q3 = (u32)(p3 * 65535.f + 0.5f);
            AhL = (q0 >> 8) | ((q1 >> 8) << 8) | ((q2 >> 8) << 16) | ((q3 >> 8) << 24);
            AlL = (q0 & 255) | ((q1 & 255) << 8) | ((q2 & 255) << 16) | ((q3 & 255) << 24);
        }
        // row r0, k-high
        {
            int4 a = *(const int4*)(adjA + jB);
            float4 f = *(const float4*)(f2h + jB);
            float p0 = __expf((a.x ? lrelu(f1a + f.x) : NEG_INF) - ma);
            float p1 = __expf((a.y ? lrelu(f1a + f.y) : NEG_INF) - ma);
            float p2 = __expf((a.z ? lrelu(f1a + f.z) : NEG_INF) - ma);
            float p3 = __expf((a.w ? lrelu(f1a + f.w) : NEG_INF) - ma);
            z0 += (p0 + p1) + (p2 + p3);
            u32 q0 = (u32)(p0 * 65535.f + 0.5f), q1 = (u32)(p1 * 65535.f + 0.5f);
            u32 q2 = (u32)(p2 * 65535.f + 0.5f), q3 = (u32)(p3 * 65535.f + 0.5f);
            AhH = (q0 >> 8) | ((q1 >> 8) << 8) | ((q2 >> 8) << 16) | ((q3 >> 8) << 24);
            AlH = (q0 & 255) | ((q1 & 255) << 8) | ((q2 & 255) << 16) | ((q3 & 255) << 24);
        }
        // row r1, k-low
        {
            int4 a = *(const int4*)(adjB + jA);
            float4 f = *(const float4*)(f2h + jA);
            float p0 = __expf((a.x ? lrelu(f1b + f.x) : NEG_INF) - mb);
            float p1 = __expf((a.y ? lrelu(f1b + f.y) : NEG_INF) - mb);
            float p2 = __expf((a.z ? lrelu(f1b + f.z) : NEG_INF) - mb);
            float p3 = __expf((a.w ? lrelu(f1b + f.w) : NEG_INF) - mb);
            z1 += (p0 + p1) + (p2 + p3);
            u32 q0 = (u32)(p0 * 65535.f + 0.5f), q1 = (u32)(p1 * 65535.f + 0.5f);
            u32 q2 = (u32)(p2 * 65535.f + 0.5f), q3 = (u32)(p3 * 65535.f + 0.5f);
            BhL = (q0 >> 8) | ((q1 >> 8) << 8) | ((q2 >> 8) << 16) | ((q3 >> 8) << 24);
            BlL = (q0 & 255) | ((q1 & 255) << 8) | ((q2 & 255) << 16) | ((q3 & 255) << 24);
        }
        // row r1, k-high
        {
            int4 a = *(const int4*)(adjB + jB);
            float4 f = *(const float4*)(f2h + jB);
            float p0 = __expf((a.x ? lrelu(f1b + f.x) : NEG_INF) - mb);
            float p1 = __expf((a.y ? lrelu(f1b + f.y) : NEG_INF) - mb);
            float p2 = __expf((a.z ? lrelu(f1b + f.z) : NEG_INF) - mb);
            float p3 = __expf((a.w ? lrelu(f1b + f.w) : NEG_INF) - mb);
            z1 += (p0 + p1) + (p2 + p3);
            u32 q0 = (u32)(p0 * 65535.f + 0.5f), q1 = (u32)(p1 * 65535.f + 0.5f);
            u32 q2 = (u32)(p2 * 65535.f + 0.5f), q3 = (u32)(p3 * 65535.f + 0.5f);
            BhH = (q0 >> 8) | ((q1 >> 8) << 8) | ((q2 >> 8) << 16) | ((q3 >> 8) << 24);
            BlH = (q0 & 255) | ((q1 & 255) << 8) | ((q2 & 255) << 16) | ((q3 & 255) << 24);
        }

        const uint4* bp = bf + (size_t)c * NT * 32;
#pragma unroll
        for (int t = 0; t < NT; t++) {
            uint4 b = bp[t * 32];
            MMA_I8(acch[t], AhL, BhL, AhH, BhH, b.x, b.y);   // hi*hi  (scale 2^16)
            MMA_I8(accm[t], AhL, BhL, AhH, BhH, b.z, b.w);   // hi*lo  (scale 2^8)
            MMA_I8(accm[t], AlL, BlL, AlH, BlH, b.x, b.y);   // lo*hi  (scale 2^8)
        }
    }

    z0 += __shfl_xor_sync(0xffffffffu, z0, 1);
    z0 += __shfl_xor_sync(0xffffffffu, z0, 2);
    z1 += __shfl_xor_sync(0xffffffffu, z1, 1);
    z1 += __shfl_xor_sync(0xffffffffu, z1, 2);
    const float iz0 = 1.f / z0;
    const float iz1 = 1.f / z1;

    const int colOff = h * colOffMult;
    float* row0 = out + (size_t)r0 * ldOut + colOff + tg * 2;
    float* row1 = out + (size_t)r1 * ldOut + colOff + tg * 2;
#pragma unroll
    for (int t = 0; t < NT; t++) {
        const int d0 = t * 8 + tg * 2;
        const float is0 = 1.f / (65535.f * Sh[d0]);
        const float is1 = 1.f / (65535.f * Sh[d0 + 1]);
        float2 v0, v1;
        v0.x = elu_f((65536.f * (float)acch[t][0] + 256.f * (float)accm[t][0]) * is0 * iz0);
        v0.y = elu_f((65536.f * (float)acch[t][1] + 256.f * (float)accm[t][1]) * is1 * iz0);
        v1.x = elu_f((65536.f * (float)acch[t][2] + 256.f * (float)accm[t][2]) * is0 * iz1);
        v1.y = elu_f((65536.f * (float)acch[t][3] + 256.f * (float)accm[t][3]) * is1 * iz1);
        *(float2*)(row0 + t * 8) = v0;
        *(float2*)(row1 + t * 8) = v1;
    }
}

// ---------------- final log_softmax over 64 classes ----------------
__global__ void lsm_kernel(const float* __restrict__ in, float* __restrict__ out)
{
    int warp = (blockIdx.x * blockDim.x + threadIdx.x) >> 5;
    int lane = threadIdx.x & 31;
    if (warp >= N_NODES) return;
    const float* row = in + (long)warp * NCLASS;
    float v0 = row[lane];
    float v1 = row[lane + 32];
    float m = fmaxf(v0, v1);
#pragma unroll
    for (int o = 16; o > 0; o >>= 1) m = fmaxf(m, __shfl_xor_sync(0xffffffffu, m, o));
    float s = expf(v0 - m) + expf(v1 - m);
#pragma unroll
    for (int o = 16; o > 0; o >>= 1) s += __shfl_xor_sync(0xffffffffu, s, o);
    float ls = m + logf(s);
    out[(long)warp * NCLASS + lane]      = v0 - ls;
    out[(long)warp * NCLASS + lane + 32] = v1 - ls;
}

// ---------------- launch ----------------
extern "C" void kernel_launch(void* const* d_in, const int* in_sizes, int n_in,
                              void* d_out, int out_size)
{
    const float* x   = (const float*)d_in[0];
    const int*   adj = (const int*)  d_in[1];
    const float* W   = (const float*)d_in[2];
    const float* a1  = (const float*)d_in[3];
    const float* a2  = (const float*)d_in[4];
    const float* Wo  = (const float*)d_in[5];
    const float* ao1 = (const float*)d_in[6];
    const float* ao2 = (const float*)d_in[7];
    float* out = (float*)d_out;

    float *Wh, *f1, *f2, *m, *hcat, *Who, *g1d, *g2d, *mo, *obuf, *S1, *S2;
    uint4 *wfrag, *wofrag, *iwhf, *iwhof;
    cudaGetSymbolAddress((void**)&Wh,     g_Wh);
    cudaGetSymbolAddress((void**)&f1,     g_f1);
    cudaGetSymbolAddress((void**)&f2,     g_f2);
    cudaGetSymbolAddress((void**)&m,      g_m);
    cudaGetSymbolAddress((void**)&hcat,   g_hcat);
    cudaGetSymbolAddress((void**)&Who,    g_Who);
    cudaGetSymbolAddress((void**)&g1d,    g_g1);
    cudaGetSymbolAddress((void**)&g2d,    g_g2);
    cudaGetSymbolAddress((void**)&mo,     g_mo);
    cudaGetSymbolAddress((void**)&obuf,   g_obuf);
    cudaGetSymbolAddress((void**)&S1,     g_S1);
    cudaGetSymbolAddress((void**)&S2,     g_S2);
    cudaGetSymbolAddress((void**)&wfrag,  g_wfrag);
    cudaGetSymbolAddress((void**)&wofrag, g_wofrag);
    cudaGetSymbolAddress((void**)&iwhf,   g_iwhf);
    cudaGetSymbolAddress((void**)&iwhof,  g_iwhof);

    // ---- layer 1 ----
    // pack W into bf16 fragments; Wh = x @ W (split-bf16 tensor path)
    {
        dim3 gp(NC16, NHEADS);
        prep_bf16_kernel<<<gp, 512>>>(W, wfrag, NHID);
        dim3 gg(N_NODES / 128, NHEADS);
        gemm_bf3_kernel<16><<<gg, 256>>>(x, wfrag, Wh, (long)N_NODES * NHID);
    }
    // f1, f2; row maxima via monotone lrelu
    dots_kernel<<<(NHEADS * N_NODES) / 8, 256>>>(Wh, a1, a2, f1, f2, NHID, N_NODES, NHEADS * N_NODES);
    maxstat_kernel<<<N_NODES, 256>>>(adj, f1, f2, m);
    // int8 scales + fragments for Wh; int8 attention apply (+Z, ELU, concat)
    colmax_kernel<<<NHEADS, 512, 512 * sizeof(float)>>>(Wh, S1, N_NODES, NHID);
    {
        dim3 gp(NCH32, NHEADS);
        prep_i8_kernel<<<gp, 512>>>(Wh, S1, iwhf, NHID);
        dim3 ga(N_NODES / 64, NHEADS);
        agg_i8_kernel<16><<<ga, 128>>>(adj, f1, f2, m, iwhf, S1, hcat,
                                       NHEADS * NHID, NHID);
    }
    // ---- layer 2 ----
    // Who = hcat @ Wo (split-bf16 tensor path)
    {
        dim3 gp(NC16, 1);
        prep_bf16_kernel<<<gp, 256>>>(Wo, wofrag, NCLASS);
        dim3 gg(N_NODES / 128, 1);
        gemm_bf3_kernel<8><<<gg, 256>>>(hcat, wofrag, Who, 0);
    }
    dots_kernel<<<N_NODES / 8, 256>>>(Who, ao1, ao2, g1d, g2d, NCLASS, N_NODES, N_NODES);
    maxstat1_kernel<<<N_NODES, 256>>>(adj, g1d, g2d, mo);
    colmax_kernel<<<1, 512, 512 * sizeof(float)>>>(Who, S2, N_NODES, NCLASS);
    {
        dim3 gp(NCH32, 1);
        prep_i8_kernel<<<gp, 256>>>(Who, S2, iwhof, NCLASS);
        dim3 ga(N_NODES / 64, 1);
        agg_i8_kernel<8><<<ga, 128>>>(adj, g1d, g2d, mo, iwhof, S2, obuf, NCLASS, 0);
    }
    // log_softmax -> d_out
    lsm_kernel<<<N_NODES / 8, 256>>>(obuf, out);
}

// round 8
// speedup vs baseline: 2.1946x; 2.1946x over previous
#include <cuda_runtime.h>
#include <cuda_bf16.h>
#include <math.h>
#include <stdint.h>

#define N_NODES 4096
#define NFEAT   1024
#define NHID    128
#define NHEADS  8
#define NCLASS  64
#define ALPHA   0.2f
#define NEG_INF -9e15f
#define NWORDS  (N_NODES / 32)   // 128 adjacency bitmask words per row

typedef uint32_t u32;

// ---------------- scratch (static device memory; no allocation) ----------------
__device__ u32    g_bits [N_NODES * NWORDS];           // 2 MB adjacency bitmask
__device__ float  g_Wh   [NHEADS * N_NODES * NHID];    // 16 MB
__device__ float  g_f1   [NHEADS * N_NODES];
__device__ float  g_f2   [NHEADS * N_NODES];
__device__ float  g_m    [NHEADS * N_NODES];
__device__ float  g_c1   [NHEADS];
__device__ float2 g_e1   [NHEADS * N_NODES];
__device__ float2 g_e2   [NHEADS * N_NODES];
__device__ float  g_hcat [N_NODES * NHEADS * NHID];    // 16 MB
__device__ float  g_Who  [N_NODES * NCLASS];
__device__ float  g_g1   [N_NODES];
__device__ float  g_g2   [N_NODES];
__device__ float  g_mo   [N_NODES];
__device__ float  g_c2   [1];
__device__ float2 g_e1o  [N_NODES];
__device__ float2 g_e2o  [N_NODES];
__device__ float  g_obuf [N_NODES * NCLASS];
// bf16 (hi only) B fragments
__device__ uint2  g_wfrag [NHEADS * (NFEAT/16) * (NHID/8) * 32];    // W:   2 MB
__device__ uint2  g_wofrag[(NFEAT/16) * (NCLASS/8) * 32];           // Wo:  128 KB
__device__ uint2  g_whf   [NHEADS * (N_NODES/16) * (NHID/8) * 32];  // Wh:  8 MB
__device__ uint2  g_whof  [(N_NODES/16) * (NCLASS/8) * 32];         // Who: 512 KB

__device__ __forceinline__ float lrelu(float x) { return fmaxf(x, ALPHA * x); }
__device__ __forceinline__ float elu_f(float x) { return x > 0.f ? x : expm1f(x); }

__device__ __forceinline__ u32 pack_bf2(float lo, float hi) {
    __nv_bfloat162 v;
    v.x = __float2bfloat16(lo);
    v.y = __float2bfloat16(hi);
    return *(u32*)&v;
}

#define MMA_BF16(ac, A0, A1, A2, A3, B0, B1) \
    asm volatile("mma.sync.aligned.m16n8k16.row.col.f32.bf16.bf16.f32 " \
                 "{%0,%1,%2,%3},{%4,%5,%6,%7},{%8,%9},{%0,%1,%2,%3};" \
                 : "+f"((ac)[0]), "+f"((ac)[1]), "+f"((ac)[2]), "+f"((ac)[3]) \
                 : "r"(A0), "r"(A1), "r"(A2), "r"(A3), "r"(B0), "r"(B1))

// ---------------- adjacency -> bitmask ----------------
__global__ void pack_adj_kernel(const int* __restrict__ adj, u32* __restrict__ bits)
{
    const int row = blockIdx.x, wid = threadIdx.x >> 5, lane = threadIdx.x & 31;
    for (int wq = wid; wq < NWORDS; wq += 8) {
        int j = wq * 32 + lane;
        u32 b = __ballot_sync(0xffffffffu, adj[(size_t)row * N_NODES + j] != 0);
        if (lane == 0) bits[row * NWORDS + wq] = b;
    }
}

// ---------------- prep: fp32 [h][k16-chunks*16][cols] -> bf16 B fragments -------
__global__ void prep_frag_kernel(const float* __restrict__ src, uint2* __restrict__ dst,
                                 int cols)
{
    const int c = blockIdx.x, h = blockIdx.y, tid = threadIdx.x;
    const int t = tid >> 5, l = tid & 31;
    const int tg = l & 3, g = l >> 2;
    const int NT = cols / 8;
    const int nchunk = gridDim.x;
    const float* p = src + (size_t)h * nchunk * 16 * cols
                   + (size_t)(c * 16 + tg * 2) * cols + t * 8 + g;
    uint2 v;
    v.x = pack_bf2(p[0], p[cols]);
    v.y = pack_bf2(p[8 * cols], p[9 * cols]);
    dst[((size_t)(h * nchunk + c) * NT + t) * 32 + l] = v;
}

// ---------------- 1-term bf16 GEMM with fused f-dots ----------------
// C[h] = A[4096,K] @ Bfrag[h] (K x NT*8); also o1[h][r] = C-row . v1[h], o2 likewise.
template<int NT>
__global__ void __launch_bounds__(256)
gemm1_kernel(const float* __restrict__ A, const uint2* __restrict__ bfrag,
             float* __restrict__ C, long cHead,
             const float* __restrict__ v1, const float* __restrict__ v2,
             float* __restrict__ o1, float* __restrict__ o2, int K)
{
    const int tid = threadIdx.x;
    const int w = tid >> 5, lane = tid & 31;
    const int tg = lane & 3, g = lane >> 2;
    const int h = blockIdx.y;
    const int r0 = blockIdx.x * 128 + w * 16 + g;
    const int r1 = r0 + 8;
    const int ldC = NT * 8;
    const int chunks = K / 16;

    const float* A0 = A + (size_t)r0 * K;
    const float* A1 = A + (size_t)r1 * K;
    const uint2* bf = bfrag + (size_t)h * chunks * NT * 32 + lane;

    float acc[NT][4];
#pragma unroll
    for (int t = 0; t < NT; t++)
#pragma unroll
        for (int q = 0; q < 4; q++) acc[t][q] = 0.f;

    for (int c = 0; c < chunks; c++) {
        const int kA = c * 16 + tg * 2;
        const int kB = kA + 8;
        float2 x0 = *(const float2*)(A0 + kA);
        float2 x1 = *(const float2*)(A1 + kA);
        float2 x2 = *(const float2*)(A0 + kB);
        float2 x3 = *(const float2*)(A1 + kB);
        u32 a0 = pack_bf2(x0.x, x0.y);
        u32 a1 = pack_bf2(x1.x, x1.y);
        u32 a2 = pack_bf2(x2.x, x2.y);
        u32 a3 = pack_bf2(x3.x, x3.y);
        const uint2* bp = bf + (size_t)c * NT * 32;
#pragma unroll
        for (int t = 0; t < NT; t++) {
            uint2 b = bp[t * 32];
            MMA_BF16(acc[t], a0, a1, a2, a3, b.x, b.y);
        }
    }

    // write C
    float* c0 = C + (size_t)h * cHead + (size_t)r0 * ldC + tg * 2;
    float* c1 = C + (size_t)h * cHead + (size_t)r1 * ldC + tg * 2;
#pragma unroll
    for (int t = 0; t < NT; t++) {
        *(float2*)(c0 + t * 8) = make_float2(acc[t][0], acc[t][1]);
        *(float2*)(c1 + t * 8) = make_float2(acc[t][2], acc[t][3]);
    }

    // fused dots with v1, v2
    const float* w1 = v1 + h * ldC;
    const float* w2 = v2 + h * ldC;
    float s10 = 0.f, s11 = 0.f, s20 = 0.f, s21 = 0.f;
#pragma unroll
    for (int t = 0; t < NT; t++) {
        const int d = t * 8 + tg * 2;
        float u0 = w1[d], u1 = w1[d + 1];
        float q0 = w2[d], q1 = w2[d + 1];
        s10 += acc[t][0] * u0 + acc[t][1] * u1;
        s11 += acc[t][2] * u0 + acc[t][3] * u1;
        s20 += acc[t][0] * q0 + acc[t][1] * q1;
        s21 += acc[t][2] * q0 + acc[t][3] * q1;
    }
#pragma unroll
    for (int o = 1; o <= 2; o <<= 1) {
        s10 += __shfl_xor_sync(0xffffffffu, s10, o);
        s11 += __shfl_xor_sync(0xffffffffu, s11, o);
        s20 += __shfl_xor_sync(0xffffffffu, s20, o);
        s21 += __shfl_xor_sync(0xffffffffu, s21, o);
    }
    if (tg == 0) {
        o1[h * N_NODES + r0] = s10;
        o1[h * N_NODES + r1] = s11;
        o2[h * N_NODES + r0] = s20;
        o2[h * N_NODES + r1] = s21;
    }
}

// ---------------- layer-1 masked max (bitmask, 8 heads) ----------------
__global__ void maxstat8_kernel(const u32* __restrict__ bits, const float* __restrict__ f1,
                                const float* __restrict__ f2, float* __restrict__ mout)
{
    __shared__ float sred[8 * 8];
    const int i = blockIdx.x, tid = threadIdx.x, wid = tid >> 5, lane = tid & 31;
    float mx[8];
#pragma unroll
    for (int h = 0; h < 8; h++) mx[h] = -INFINITY;
    const u32* brow = bits + (size_t)i * NWORDS;
    for (int q = tid; q < N_NODES / 4; q += 256) {
        u32 nib = (brow[q >> 3] >> ((q & 7) * 4)) & 15u;
        if (!nib) continue;
        int j = q * 4;
#pragma unroll
        for (int h = 0; h < 8; h++) {
            float4 fv = *(const float4*)(f2 + h * N_NODES + j);
            if (nib & 1u) mx[h] = fmaxf(mx[h], fv.x);
            if (nib & 2u) mx[h] = fmaxf(mx[h], fv.y);
            if (nib & 4u) mx[h] = fmaxf(mx[h], fv.z);
            if (nib & 8u) mx[h] = fmaxf(mx[h], fv.w);
        }
    }
#pragma unroll
    for (int h = 0; h < 8; h++)
#pragma unroll
        for (int o = 16; o > 0; o >>= 1) mx[h] = fmaxf(mx[h], __shfl_xor_sync(0xffffffffu, mx[h], o));
    if (lane == 0)
#pragma unroll
        for (int h = 0; h < 8; h++) sred[h * 8 + wid] = mx[h];
    __syncthreads();
    if (tid < 8) {
        float m2 = sred[tid * 8];
#pragma unroll
        for (int w = 1; w < 8; w++) m2 = fmaxf(m2, sred[tid * 8 + w]);
        mout[tid * N_NODES + i] = (m2 == -INFINITY) ? NEG_INF
                                                    : lrelu(f1[tid * N_NODES + i] + m2);
    }
}

// ---------------- layer-2 masked max (bitmask, 1 head) ----------------
__global__ void maxstat1_kernel(const u32* __restrict__ bits, const float* __restrict__ g1,
                                const float* __restrict__ g2, float* __restrict__ mout)
{
    __shared__ float sred[8];
    const int i = blockIdx.x, tid = threadIdx.x, wid = tid >> 5, lane = tid & 31;
    float mx = -INFINITY;
    const u32* brow = bits + (size_t)i * NWORDS;
    for (int q = tid; q < N_NODES / 4; q += 256) {
        u32 nib = (brow[q >> 3] >> ((q & 7) * 4)) & 15u;
        if (!nib) continue;
        float4 fv = *(const float4*)(g2 + q * 4);
        if (nib & 1u) mx = fmaxf(mx, fv.x);
        if (nib & 2u) mx = fmaxf(mx, fv.y);
        if (nib & 4u) mx = fmaxf(mx, fv.z);
        if (nib & 8u) mx = fmaxf(mx, fv.w);
    }
#pragma unroll
    for (int o = 16; o > 0; o >>= 1) mx = fmaxf(mx, __shfl_xor_sync(0xffffffffu, mx, o));
    if (lane == 0) sred[wid] = mx;
    __syncthreads();
    if (tid == 0) {
        float m2 = sred[0];
        for (int w = 1; w < 8; w++) m2 = fmaxf(m2, sred[w]);
        mout[i] = (m2 == -INFINITY) ? NEG_INF : lrelu(g1[i] + m2);
    }
}

// ---------------- per-head unmasked max of f2 ----------------
__global__ void headmax_kernel(const float* __restrict__ v, float* __restrict__ c)
{
    __shared__ float red[256];
    const int h = blockIdx.x, tid = threadIdx.x;
    float mx = -INFINITY;
    for (int j = tid; j < N_NODES; j += 256) mx = fmaxf(mx, v[h * N_NODES + j]);
    red[tid] = mx;
    __syncthreads();
    for (int s = 128; s > 0; s >>= 1) {
        if (tid < s) red[tid] = fmaxf(red[tid], red[tid + s]);
        __syncthreads();
    }
    if (tid == 0) c[h] = red[0];
}

// ---------------- precompute factorized exp tables ----------------
// P_ij (pos branch) = e1[i].x * e2[j].x ; (neg branch) = e1[i].y * e2[j].y
__global__ void fill_e_kernel(const float* __restrict__ f1, const float* __restrict__ f2,
                              const float* __restrict__ m, const float* __restrict__ c,
                              float2* __restrict__ e1, float2* __restrict__ e2)
{
    const int idx = blockIdx.x * 256 + threadIdx.x;
    const int h = idx >> 12;
    const float ch = c[h];
    const float F1 = f1[idx], F2 = f2[idx], M = m[idx];
    e1[idx] = make_float2(__expf(F1 + ch - M), __expf(0.2f * (F1 + ch) - M));
    e2[idx] = make_float2(__expf(F2 - ch), __expf(0.2f * (F2 - ch)));
}

// ---------------- factorized-exp 1-term bf16 attention apply ----------------
__device__ __forceinline__ float pval(u32 w, int sh, float f1v, float f2v,
                                      float2 E1, float ep, float en)
{
    bool pos = (f1v + f2v) > 0.f;
    float p = (pos ? E1.x : E1.y) * (pos ? ep : en);
    return ((w >> sh) & 1u) ? p : 0.f;
}

template<int NT>
__global__ void __launch_bounds__(256)
agg1_kernel(const u32* __restrict__ bits, const float* __restrict__ f1,
            const float* __restrict__ f2, const float2* __restrict__ e1,
            const float2* __restrict__ e2, const uint2* __restrict__ bfrag,
            float* __restrict__ out, int ldOut, int colMult)
{
    const int tid = threadIdx.x;
    const int w = tid >> 5, lane = tid & 31;
    const int tg = lane & 3, g = lane >> 2;
    const int h = blockIdx.y;
    const int hN = h * N_NODES;
    const int r0 = blockIdx.x * 128 + w * 16 + g;
    const int r1 = r0 + 8;

    const float f1a = f1[hN + r0], f1b = f1[hN + r1];
    const float2 E1a = e1[hN + r0], E1b = e1[hN + r1];
    const float* f2h = f2 + hN;
    const float2* e2h = e2 + hN;
    const u32* rowA = bits + (size_t)r0 * NWORDS;
    const u32* rowB = bits + (size_t)r1 * NWORDS;
    const uint2* bf = bfrag + (size_t)h * (N_NODES / 16) * NT * 32 + lane;

    float acc[NT][4];
#pragma unroll
    for (int t = 0; t < NT; t++)
#pragma unroll
        for (int q = 0; q < 4; q++) acc[t][q] = 0.f;

    float z0 = 0.f, z1 = 0.f;
    u32 wA = 0, wB = 0;

    for (int c = 0; c < N_NODES / 16; c++) {
        if ((c & 1) == 0) { wA = rowA[c >> 1]; wB = rowB[c >> 1]; }
        const int sh = (c & 1) * 16 + tg * 2;
        const int jA = c * 16 + tg * 2;
        const int jB = jA + 8;

        float2 fA = *(const float2*)(f2h + jA);
        float2 fB = *(const float2*)(f2h + jB);
        float4 eA = *(const float4*)(e2h + jA);   // (p_jA, n_jA, p_jA+1, n_jA+1)
        float4 eB = *(const float4*)(e2h + jB);

        float p00 = pval(wA, sh,     f1a, fA.x, E1a, eA.x, eA.y);
        float p01 = pval(wA, sh + 1, f1a, fA.y, E1a, eA.z, eA.w);
        float p02 = pval(wA, sh + 8, f1a, fB.x, E1a, eB.x, eB.y);
        float p03 = pval(wA, sh + 9, f1a, fB.y, E1a, eB.z, eB.w);
        float p10 = pval(wB, sh,     f1b, fA.x, E1b, eA.x, eA.y);
        float p11 = pval(wB, sh + 1, f1b, fA.y, E1b, eA.z, eA.w);
        float p12 = pval(wB, sh + 8, f1b, fB.x, E1b, eB.x, eB.y);
        float p13 = pval(wB, sh + 9, f1b, fB.y, E1b, eB.z, eB.w);

        // round to bf16; Z accumulates the ROUNDED values (consistent with MMA)
        __nv_bfloat16 b00 = __float2bfloat16(p00), b01 = __float2bfloat16(p01);
        __nv_bfloat16 b02 = __float2bfloat16(p02), b03 = __float2bfloat16(p03);
        __nv_bfloat16 b10 = __float2bfloat16(p10), b11 = __float2bfloat16(p11);
        __nv_bfloat16 b12 = __float2bfloat16(p12), b13 = __float2bfloat16(p13);
        z0 += (__bfloat162float(b00) + __bfloat162float(b01))
            + (__bfloat162float(b02) + __bfloat162float(b03));
        z1 += (__bfloat162float(b10) + __bfloat162float(b11))
            + (__bfloat162float(b12) + __bfloat162float(b13));

        __nv_bfloat162 v0; v0.x = b00; v0.y = b01;
        __nv_bfloat162 v1; v1.x = b10; v1.y = b11;
        __nv_bfloat162 v2; v2.x = b02; v2.y = b03;
        __nv_bfloat162 v3; v3.x = b12; v3.y = b13;
        u32 a0 = *(u32*)&v0, a1 = *(u32*)&v1, a2 = *(u32*)&v2, a3 = *(u32*)&v3;

        const uint2* bp = bf + (size_t)c * NT * 32;
#pragma unroll
        for (int t = 0; t < NT; t++) {
            uint2 b = bp[t * 32];
            MMA_BF16(acc[t], a0, a1, a2, a3, b.x, b.y);
        }
    }

    z0 += __shfl_xor_sync(0xffffffffu, z0, 1);
    z0 += __shfl_xor_sync(0xffffffffu, z0, 2);
    z1 += __shfl_xor_sync(0xffffffffu, z1, 1);
    z1 += __shfl_xor_sync(0xffffffffu, z1, 2);
    const float iz0 = 1.f / z0;
    const float iz1 = 1.f / z1;

    float* row0 = out + (size_t)r0 * ldOut + h * colMult + tg * 2;
    float* row1 = out + (size_t)r1 * ldOut + h * colMult + tg * 2;
#pragma unroll
    for (int t = 0; t < NT; t++) {
        float2 v0, v1;
        v0.x = elu_f(acc[t][0] * iz0);
        v0.y = elu_f(acc[t][1] * iz0);
        v1.x = elu_f(acc[t][2] * iz1);
        v1.y = elu_f(acc[t][3] * iz1);
        *(float2*)(row0 + t * 8) = v0;
        *(float2*)(row1 + t * 8) = v1;
    }
}

// ---------------- final log_softmax over 64 classes ----------------
__global__ void lsm_kernel(const float* __restrict__ in, float* __restrict__ out)
{
    int warp = (blockIdx.x * blockDim.x + threadIdx.x) >> 5;
    int lane = threadIdx.x & 31;
    if (warp >= N_NODES) return;
    const float* row = in + (long)warp * NCLASS;
    float v0 = row[lane];
    float v1 = row[lane + 32];
    float m = fmaxf(v0, v1);
#pragma unroll
    for (int o = 16; o > 0; o >>= 1) m = fmaxf(m, __shfl_xor_sync(0xffffffffu, m, o));
    float s = expf(v0 - m) + expf(v1 - m);
#pragma unroll
    for (int o = 16; o > 0; o >>= 1) s += __shfl_xor_sync(0xffffffffu, s, o);
    float ls = m + logf(s);
    out[(long)warp * NCLASS + lane]      = v0 - ls;
    out[(long)warp * NCLASS + lane + 32] = v1 - ls;
}

// ---------------- launch ----------------
extern "C" void kernel_launch(void* const* d_in, const int* in_sizes, int n_in,
                              void* d_out, int out_size)
{
    const float* x   = (const float*)d_in[0];
    const int*   adj = (const int*)  d_in[1];
    const float* W   = (const float*)d_in[2];
    const float* a1  = (const float*)d_in[3];
    const float* a2  = (const float*)d_in[4];
    const float* Wo  = (const float*)d_in[5];
    const float* ao1 = (const float*)d_in[6];
    const float* ao2 = (const float*)d_in[7];
    float* out = (float*)d_out;

    u32* bits;
    float *Wh, *f1, *f2, *m, *c1, *hcat, *Who, *g1, *g2, *mo, *c2, *obuf;
    float2 *e1, *e2, *e1o, *e2o;
    uint2 *wfrag, *wofrag, *whf, *whof;
    cudaGetSymbolAddress((void**)&bits,   g_bits);
    cudaGetSymbolAddress((void**)&Wh,     g_Wh);
    cudaGetSymbolAddress((void**)&f1,     g_f1);
    cudaGetSymbolAddress((void**)&f2,     g_f2);
    cudaGetSymbolAddress((void**)&m,      g_m);
    cudaGetSymbolAddress((void**)&c1,     g_c1);
    cudaGetSymbolAddress((void**)&e1,     g_e1);
    cudaGetSymbolAddress((void**)&e2,     g_e2);
    cudaGetSymbolAddress((void**)&hcat,   g_hcat);
    cudaGetSymbolAddress((void**)&Who,    g_Who);
    cudaGetSymbolAddress((void**)&g1,     g_g1);
    cudaGetSymbolAddress((void**)&g2,     g_g2);
    cudaGetSymbolAddress((void**)&mo,     g_mo);
    cudaGetSymbolAddress((void**)&c2,     g_c2);
    cudaGetSymbolAddress((void**)&e1o,    g_e1o);
    cudaGetSymbolAddress((void**)&e2o,    g_e2o);
    cudaGetSymbolAddress((void**)&obuf,   g_obuf);
    cudaGetSymbolAddress((void**)&wfrag,  g_wfrag);
    cudaGetSymbolAddress((void**)&wofrag, g_wofrag);
    cudaGetSymbolAddress((void**)&whf,    g_whf);
    cudaGetSymbolAddress((void**)&whof,   g_whof);

    // adjacency bitmask
    pack_adj_kernel<<<N_NODES, 256>>>(adj, bits);

    // ---- layer 1 ----
    {
        dim3 gp(NFEAT / 16, NHEADS);
        prep_frag_kernel<<<gp, 512>>>(W, wfrag, NHID);
        dim3 gg(N_NODES / 128, NHEADS);
        gemm1_kernel<16><<<gg, 256>>>(x, wfrag, Wh, (long)N_NODES * NHID,
                                      a1, a2, f1, f2, NFEAT);
    }
    maxstat8_kernel<<<N_NODES, 256>>>(bits, f1, f2, m);
    headmax_kernel<<<NHEADS, 256>>>(f2, c1);
    fill_e_kernel<<<(NHEADS * N_NODES) / 256, 256>>>(f1, f2, m, c1, e1, e2);
    {
        dim3 gp(N_NODES / 16, NHEADS);
        prep_frag_kernel<<<gp, 512>>>(Wh, whf, NHID);
        dim3 ga(N_NODES / 128, NHEADS);
        agg1_kernel<16><<<ga, 256>>>(bits, f1, f2, e1, e2, whf, hcat,
                                     NHEADS * NHID, NHID);
    }
    // ---- layer 2 ----
    {
        dim3 gp(NFEAT / 16, 1);
        prep_frag_kernel<<<gp, 256>>>(Wo, wofrag, NCLASS);
        dim3 gg(N_NODES / 128, 1);
        gemm1_kernel<8><<<gg, 256>>>(hcat, wofrag, Who, 0,
                                     ao1, ao2, g1, g2, NFEAT);
    }
    maxstat1_kernel<<<N_NODES, 256>>>(bits, g1, g2, mo);
    headmax_kernel<<<1, 256>>>(g2, c2);
    fill_e_kernel<<<N_NODES / 256, 256>>>(g1, g2, mo, c2, e1o, e2o);
    {
        dim3 gp(N_NODES / 16, 1);
        prep_frag_kernel<<<gp, 256>>>(Who, whof, NCLASS);
        dim3 ga(N_NODES / 128, 1);
        agg1_kernel<8><<<ga, 256>>>(bits, g1, g2, e1o, e2o, whof, obuf,
                                    NCLASS, 0);
    }
    lsm_kernel<<<N_NODES / 8, 256>>>(obuf, out);
}